// round 10
// baseline (speedup 1.0000x reference)
#include <cuda_runtime.h>
#include <cuda_bf16.h>
#include <cstdint>

// Problem constants
#define BB 2
#define NN 65536
#define CC 256
#define HH 8
#define DD 64
#define SS 64
#define INNERD 512
#define NTOK (BB * NN)      // 131072
#define NCTA (NTOK / 128)   // 1024

// smem word strides: A=272, B=144 (==16 mod 32, LDS.128-safe); w/f=136 (==8 mod 32, LDS.64-safe)
#define AST 272
#define BST 144
#define WST 136
#define OFF_BS 0
#define OFF_BD 256
#define OFF_A  1024
#define OFF_B  (OFF_A + 128 * AST * 4)       // 140288
#define OFF_W  OFF_B                          // 64*136*4 = 34816
#define OFF_F  (OFF_B + 64 * WST * 4)         // 175104
#define SMEM_TOTAL (OFF_B + 128 * BST * 4)    // 214016

// Device scratch
__device__ __align__(16) float g_Weff[HH][CC][SS];
__device__ __align__(16) float g_beff[HH][SS];
__device__ __align__(16) float g_acc[BB * HH * SS * DD];
__device__ __align__(16) float g_norm[BB * HH * SS];
__device__ __align__(16) float g_Btf[HH * 128 * CC];   // tf32-rounded, k16-permuted B^T images

// ---------------- helpers ----------------
__device__ __forceinline__ uint32_t cvt_tf32(float v) {
    uint32_t r;
    asm("cvt.rna.tf32.f32 %0, %1;" : "=r"(r) : "f"(v));
    return r;
}
__device__ __forceinline__ void mma_tf32(float* c, uint32_t a0, uint32_t a1,
                                         uint32_t a2, uint32_t a3,
                                         uint32_t b0, uint32_t b1) {
    asm volatile(
        "mma.sync.aligned.m16n8k8.row.col.f32.tf32.tf32.f32 "
        "{%0,%1,%2,%3}, {%4,%5,%6,%7}, {%8,%9}, {%0,%1,%2,%3};"
        : "+f"(c[0]), "+f"(c[1]), "+f"(c[2]), "+f"(c[3])
        : "r"(a0), "r"(a1), "r"(a2), "r"(a3), "r"(b0), "r"(b1));
}
__device__ __forceinline__ int perm16(int K) {
    return (K & ~15) | ((K & 3) << 2) | ((K >> 2) & 3);
}
__device__ __forceinline__ int perm8(int K) {
    return (K & ~7) | ((K & 3) << 1) | ((K >> 2) & 1);
}

// ---------------------------------------------------------------- zero
__global__ void zero_kernel() {
    int i = blockIdx.x * blockDim.x + threadIdx.x;
    if (i < BB * HH * SS * DD) g_acc[i] = 0.0f;
    if (i < BB * HH * SS)      g_norm[i] = 0.0f;
}

// ------------------------------------------------- precompute Weff/beff
__global__ void precompute_kernel(const float* __restrict__ Wx,
                                  const float* __restrict__ bx,
                                  const float* __restrict__ Wslice,
                                  const float* __restrict__ bslice) {
    int m = blockIdx.x;
    int s = threadIdx.x;
    if (m < HH * CC) {
        int h = m / CC, k = m % CC;
        float a = 0.0f;
#pragma unroll 16
        for (int d = 0; d < DD; d++)
            a += Wx[(size_t)k * INNERD + h * DD + d] * Wslice[d * SS + s];
        g_Weff[h][k][s] = a;
    } else {
        for (int h = 0; h < HH; h++) {
            float a = bslice[s];
            for (int d = 0; d < DD; d++)
                a += bx[h * DD + d] * Wslice[d * SS + s];
            g_beff[h][s] = a;
        }
    }
}

// ---- B^T images [h][n(64 s | 64 d)][K perm16], tf32-rounded
__global__ void build_bt(const float* __restrict__ Wfx) {
    int h = blockIdx.x;
    for (int i = threadIdx.x; i < 128 * 256; i += 256) {
        int n = i >> 8, K = i & 255;
        float v = (n < 64) ? g_Weff[h][K][n]
                           : Wfx[(size_t)K * INNERD + h * DD + (n - 64)];
        g_Btf[(size_t)(h * 128 + n) * 256 + perm16(K)] = __uint_as_float(cvt_tf32(v));
    }
}

// ---------------------------------------------------------------- main
extern __shared__ unsigned char smem[];

__global__ __launch_bounds__(512, 1) void fused_main(
    const float* __restrict__ x,
    const float* __restrict__ bfx,
    const float* __restrict__ temperature)
{
    const int t    = threadIdx.x;
    const int wp   = t >> 5;
    const int lane = t & 31;
    const int g    = lane >> 2;
    const int q    = lane & 3;
    const int wm   = wp & 3;          // GEMM1 m-group (32 tok)
    const int wn   = wp >> 2;         // GEMM1 n-group (32 cols): 0,1 = s; 2,3 = d
    const int ct   = blockIdx.x;
    const int tok0 = ct * 128;
    const int b    = ct >> 9;

    uint32_t* smu = (uint32_t*)smem;
    float*    smf = (float*)smem;
    const int A0 = OFF_A / 4, B0 = OFF_B / 4, W0 = OFF_W / 4, F0 = OFF_F / 4;

    // ---- stage A once: tf32-rounded, k16-permuted ----
#pragma unroll
    for (int it = 0; it < 16; it++) {
        int idx = it * 512 + t;               // 128 rows x 64 float4
        int row = idx >> 6, c4 = idx & 63;
        float4 v = *(const float4*)&x[((size_t)(tok0 + row)) * CC + c4 * 4];
        uint32_t* d = &smu[A0 + row * AST + (c4 >> 2) * 16 + (c4 & 3)];
        d[0] = cvt_tf32(v.x); d[4] = cvt_tf32(v.y);
        d[8] = cvt_tf32(v.z); d[12] = cvt_tf32(v.w);
    }
    __syncthreads();

    for (int h = 0; h < HH; h++) {
        float tmp = temperature[h];
        tmp = fminf(fmaxf(tmp, 0.5f), 5.0f);
        const float invt = __fdividef(1.0f, tmp);

        float c[2][4][4];
#pragma unroll
        for (int i = 0; i < 2; i++)
#pragma unroll
            for (int j = 0; j < 4; j++)
#pragma unroll
                for (int e = 0; e < 4; e++) c[i][j][e] = 0.0f;

        const float* img = g_Btf + (size_t)h * 128 * 256;

        // ============ GEMM1: two K-halves, synchronous staging ============
#pragma unroll
        for (int kh = 0; kh < 2; kh++) {
            // stage B half [128 n][128 k]
#pragma unroll
            for (int it = 0; it < 8; it++) {
                int idx = it * 512 + t;       // 128 rows x 32 float4
                int row = idx >> 5, c4 = idx & 31;
                float4 v = *(const float4*)&img[(size_t)row * 256 + kh * 128 + c4 * 4];
                *(float4*)&smf[B0 + row * BST + c4 * 4] = v;
            }
            if (kh == 0 && t < 64) {
                smf[OFF_BS / 4 + t] = g_beff[h][t];
                smf[OFF_BD / 4 + t] = bfx[h * DD + t];
            }
            __syncthreads();

#pragma unroll
            for (int k16 = 0; k16 < 8; k16++) {
                const int akb = (kh * 8 + k16) * 16 + 4 * q;
                uint4 a0[2], a1[2];
#pragma unroll
                for (int mt = 0; mt < 2; mt++) {
                    const int r0 = wm * 32 + mt * 16 + g;
                    a0[mt] = *(const uint4*)&smu[A0 + r0 * AST + akb];
                    a1[mt] = *(const uint4*)&smu[A0 + (r0 + 8) * AST + akb];
                }
#pragma unroll
                for (int nt = 0; nt < 4; nt++) {
                    uint4 bb = *(const uint4*)&smu[B0 + (wn * 32 + nt * 8 + g) * BST
                                                   + k16 * 16 + 4 * q];
#pragma unroll
                    for (int mt = 0; mt < 2; mt++) {
                        mma_tf32(c[mt][nt], a0[mt].x, a1[mt].x, a0[mt].y, a1[mt].y,
                                 bb.x, bb.y);
                        mma_tf32(c[mt][nt], a0[mt].z, a1[mt].z, a0[mt].w, a1[mt].w,
                                 bb.z, bb.w);
                    }
                }
            }
            __syncthreads();   // B reads done -> restage / stores
        }

        // ============ dump GEMM1 results to smem (s raw, f biased+tf32) ============
        if (wn < 2) {
#pragma unroll
            for (int mt = 0; mt < 2; mt++)
#pragma unroll
                for (int rr = 0; rr < 2; rr++) {
                    const int ptok = perm8(wm * 32 + mt * 16 + g + 8 * rr);
#pragma unroll
                    for (int nt = 0; nt < 4; nt++)
#pragma unroll
                        for (int e = 0; e < 2; e++) {
                            int s = wn * 32 + nt * 8 + 2 * q + e;
                            smf[W0 + s * WST + ptok] = c[mt][nt][rr * 2 + e];
                        }
                }
        } else {
            const float* bd = &smf[OFF_BD / 4];
#pragma unroll
            for (int mt = 0; mt < 2; mt++)
#pragma unroll
                for (int rr = 0; rr < 2; rr++) {
                    const int ptok = perm8(wm * 32 + mt * 16 + g + 8 * rr);
#pragma unroll
                    for (int nt = 0; nt < 4; nt++)
#pragma unroll
                        for (int e = 0; e < 2; e++) {
                            int d = (wn - 2) * 32 + nt * 8 + 2 * q + e;
                            smu[F0 + d * WST + ptok] = cvt_tf32(c[mt][nt][rr * 2 + e] + bd[d]);
                        }
                }
        }
        __syncthreads();

        // ============ softmax: 2 threads per token ============
        if (t < 256) {
            const int tok = t >> 1, sh = t & 1;
            const int ptok = perm8(tok);
            const float* bs = &smf[OFF_BS / 4];
            float pv[32];
            float mx = -1e30f;
#pragma unroll
            for (int j = 0; j < 32; j++) {
                int s = sh * 32 + j;
                float p = (smf[W0 + s * WST + ptok] + bs[s]) * invt;
                pv[j] = p;
                mx = fmaxf(mx, p);
            }
            mx = fmaxf(mx, __shfl_xor_sync(0xffffffffu, mx, 1));
            float sv = 0.0f;
#pragma unroll
            for (int j = 0; j < 32; j++) { pv[j] = __expf(pv[j] - mx); sv += pv[j]; }
            sv += __shfl_xor_sync(0xffffffffu, sv, 1);
            const float r = __fdividef(1.0f, sv);
#pragma unroll
            for (int j = 0; j < 32; j++)
                smu[W0 + (sh * 32 + j) * WST + ptok] = cvt_tf32(pv[j] * r);
        }
        __syncthreads();

        // ============ rank update: acc[64 s][64 d] += w^T @ fx ============
        {
            const int wm2 = wp & 3;    // s16 tile
            const int wn2 = wp >> 2;   // d16 tile
            float racc[2][4];
#pragma unroll
            for (int i = 0; i < 2; i++)
#pragma unroll
                for (int j = 0; j < 4; j++) racc[i][j] = 0.0f;

#pragma unroll 4
            for (int ks = 0; ks < 16; ks++) {
                const int kc = ks * 8 + 2 * q;
                const int r0 = wm2 * 16 + g;
                uint2 lo = *(const uint2*)&smu[W0 + r0 * WST + kc];
                uint2 hi = *(const uint2*)&smu[W0 + (r0 + 8) * WST + kc];
#pragma unroll
                for (int nt = 0; nt < 2; nt++) {
                    uint2 bb = *(const uint2*)&smu[F0 + (wn2 * 16 + nt * 8 + g) * WST + kc];
                    mma_tf32(racc[nt], lo.x, hi.x, lo.y, hi.y, bb.x, bb.y);
                }
            }

            const int abase = (b * HH + h) * SS;
#pragma unroll
            for (int nt = 0; nt < 2; nt++)
#pragma unroll
                for (int rr = 0; rr < 2; rr++)
#pragma unroll
                    for (int e = 0; e < 2; e++) {
                        int s = wm2 * 16 + g + 8 * rr;
                        int d = wn2 * 16 + nt * 8 + 2 * q + e;
                        atomicAdd(&g_acc[(abase + s) * DD + d], racc[nt][rr * 2 + e]);
                    }
        }

        // ---- norm: row-sums of w (4 rows per warp) ----
        {
            const int nb = (b * HH + h) * SS;
#pragma unroll
            for (int j = 0; j < 4; j++) {
                int s = wp * 4 + j;
                float acc = smf[W0 + s * WST + lane]
                          + smf[W0 + s * WST + lane + 32]
                          + smf[W0 + s * WST + lane + 64]
                          + smf[W0 + s * WST + lane + 96];
#pragma unroll
                for (int off = 16; off >= 1; off >>= 1)
                    acc += __shfl_xor_sync(0xffffffffu, acc, off);
                if (lane == 0) atomicAdd(&g_norm[nb + s], acc);
            }
        }
        __syncthreads();   // w/f reads done -> next head may restage B
    }
}

// ------------------------------------------------------------ finalize
__global__ void finalize_kernel(float* __restrict__ out) {
    int i = blockIdx.x * blockDim.x + threadIdx.x;
    if (i < BB * HH * SS * DD)
        out[i] = g_acc[i] / (g_norm[i >> 6] + 0.01f);
}

// -------------------------------------------------------------- launch
extern "C" void kernel_launch(void* const* d_in, const int* in_sizes, int n_in,
                              void* d_out, int out_size) {
    const float* x           = (const float*)d_in[0];
    const float* Wx          = (const float*)d_in[1];
    const float* bx          = (const float*)d_in[2];
    const float* Wfx         = (const float*)d_in[3];
    const float* bfx         = (const float*)d_in[4];
    const float* Wslice      = (const float*)d_in[5];
    const float* bslice      = (const float*)d_in[6];
    const float* temperature = (const float*)d_in[7];
    float* out = (float*)d_out;

    cudaFuncSetAttribute(fused_main, cudaFuncAttributeMaxDynamicSharedMemorySize,
                         SMEM_TOTAL);

    zero_kernel<<<(BB * HH * SS * DD + 255) / 256, 256>>>();
    precompute_kernel<<<HH * CC + 1, 64>>>(Wx, bx, Wslice, bslice);
    build_bt<<<HH, 256>>>(Wfx);
    fused_main<<<NCTA, 512, SMEM_TOTAL>>>(x, bfx, temperature);
    finalize_kernel<<<(BB * HH * SS * DD + 255) / 256, 256>>>(out);
}

// round 11
// speedup vs baseline: 1.1207x; 1.1207x over previous
#include <cuda_runtime.h>
#include <cuda_bf16.h>
#include <cstdint>

// Problem constants
#define BB 2
#define NN 65536
#define CC 256
#define HH 8
#define DD 64
#define SS 64
#define INNERD 512
#define NTOK (BB * NN)      // 131072
#define NCTA (NTOK / 128)   // 1024

// smem word offsets/strides. AST/BST ==16 mod 32 (LDS.128-safe per 8-lane phase),
// WST ==8 mod 32 (LDS.64-safe).
#define AST 272
#define BST 144
#define WST 136
#define A0W 0
#define B0W (128 * AST)            // 34816 words
#define W0W B0W                    // w aliases B (dead after GEMM1)
#define F0W (B0W + 64 * WST)       // 43520
#define SMEM_TOTAL ((B0W + 128 * BST) * 4)   // 212992 bytes

// Device scratch
__device__ __align__(16) float g_Weff[HH][CC][SS];
__device__ __align__(16) float g_beff[HH][SS];
__device__ __align__(16) float g_acc[BB * HH * SS * DD];
__device__ __align__(16) float g_norm[BB * HH * SS];
__device__ __align__(16) float g_Btf[HH * 128 * CC];   // tf32-rounded, k16-permuted B^T images

// ---------------- helpers ----------------
__device__ __forceinline__ uint32_t cvt_tf32(float v) {
    uint32_t r;
    asm("cvt.rna.tf32.f32 %0, %1;" : "=r"(r) : "f"(v));
    return r;
}
__device__ __forceinline__ void mma_tf32(float* c, uint32_t a0, uint32_t a1,
                                         uint32_t a2, uint32_t a3,
                                         uint32_t b0, uint32_t b1) {
    asm volatile(
        "mma.sync.aligned.m16n8k8.row.col.f32.tf32.tf32.f32 "
        "{%0,%1,%2,%3}, {%4,%5,%6,%7}, {%8,%9}, {%0,%1,%2,%3};"
        : "+f"(c[0]), "+f"(c[1]), "+f"(c[2]), "+f"(c[3])
        : "r"(a0), "r"(a1), "r"(a2), "r"(a3), "r"(b0), "r"(b1));
}
__device__ __forceinline__ int perm16(int K) {
    return (K & ~15) | ((K & 3) << 2) | ((K >> 2) & 3);
}
__device__ __forceinline__ int perm8(int K) {
    return (K & ~7) | ((K & 3) << 1) | ((K >> 2) & 1);
}

// ---------------------------------------------------------------- zero
__global__ void zero_kernel() {
    int i = blockIdx.x * blockDim.x + threadIdx.x;
    if (i < BB * HH * SS * DD) g_acc[i] = 0.0f;
    if (i < BB * HH * SS)      g_norm[i] = 0.0f;
}

// ------------------------------------------------- precompute Weff/beff
__global__ void precompute_kernel(const float* __restrict__ Wx,
                                  const float* __restrict__ bx,
                                  const float* __restrict__ Wslice,
                                  const float* __restrict__ bslice) {
    int m = blockIdx.x;
    int s = threadIdx.x;
    if (m < HH * CC) {
        int h = m / CC, k = m % CC;
        float a = 0.0f;
#pragma unroll 16
        for (int d = 0; d < DD; d++)
            a += Wx[(size_t)k * INNERD + h * DD + d] * Wslice[d * SS + s];
        g_Weff[h][k][s] = a;
    } else {
        for (int h = 0; h < HH; h++) {
            float a = bslice[s];
            for (int d = 0; d < DD; d++)
                a += bx[h * DD + d] * Wslice[d * SS + s];
            g_beff[h][s] = a;
        }
    }
}

// ---- B^T images [h][n(64 s | 64 d)][K perm16], tf32-rounded
__global__ void build_bt(const float* __restrict__ Wfx) {
    int h = blockIdx.x;
    for (int i = threadIdx.x; i < 128 * 256; i += 256) {
        int n = i >> 8, K = i & 255;
        float v = (n < 64) ? g_Weff[h][K][n]
                           : Wfx[(size_t)K * INNERD + h * DD + (n - 64)];
        g_Btf[(size_t)(h * 128 + n) * 256 + perm16(K)] = __uint_as_float(cvt_tf32(v));
    }
}

// ---------------------------------------------------------------- main
extern __shared__ unsigned char smem[];

__global__ __launch_bounds__(256, 1) void fused_main(
    const float* __restrict__ x,
    const float* __restrict__ bfx,
    const float* __restrict__ temperature)
{
    const int t    = threadIdx.x;
    const int wp   = t >> 5;
    const int lane = t & 31;
    const int g    = lane >> 2;
    const int q    = lane & 3;
    const int wml  = wp & 3;          // m-group (32 tok)
    const int wn   = wp >> 2;         // 0: s-half (n 0..63), 1: d-half
    const int ct   = blockIdx.x;
    const int tok0 = ct * 128;
    const int b    = ct >> 9;

    uint32_t* smu = (uint32_t*)smem;
    float*    smf = (float*)smem;

    // ---- stage A once: tf32-rounded, k16-permuted ----
    for (int it = 0; it < 32; it++) {
        int idx = it * 256 + t;               // 128 rows x 64 float4
        int row = idx >> 6, c4 = idx & 63;
        float4 v = *(const float4*)&x[((size_t)(tok0 + row)) * CC + c4 * 4];
        uint32_t* d = &smu[A0W + row * AST + (c4 >> 2) * 16 + (c4 & 3)];
        d[0] = cvt_tf32(v.x); d[4]  = cvt_tf32(v.y);
        d[8] = cvt_tf32(v.z); d[12] = cvt_tf32(v.w);
    }
    __syncthreads();

    // hoisted row offsets
    const int ar0 = (wml * 32 + g) * AST;          // mt=0, lower
    const int ar1 = ar0 + 8 * AST;                 // mt=0, upper
    const int ar2 = ar0 + 16 * AST;                // mt=1, lower
    const int ar3 = ar0 + 24 * AST;                // mt=1, upper
    const int brow = (wn * 64 + g) * BST + 4 * q;  // + nt*8*BST + k16*16

    for (int h = 0; h < HH; h++) {
        float tmp = temperature[h];
        tmp = fminf(fmaxf(tmp, 0.5f), 5.0f);
        const float invt = __fdividef(1.0f, tmp);
        float bias16[16];
#pragma unroll
        for (int nt = 0; nt < 8; nt++)
#pragma unroll
            for (int e = 0; e < 2; e++)
                bias16[nt * 2 + e] = wn ? bfx[h * DD + nt * 8 + 2 * q + e]
                                        : g_beff[h][nt * 8 + 2 * q + e];

        float c[2][8][4];
#pragma unroll
        for (int i = 0; i < 2; i++)
#pragma unroll
            for (int j = 0; j < 8; j++)
#pragma unroll
                for (int e = 0; e < 4; e++) c[i][j][e] = 0.0f;

        const float* img = g_Btf + (size_t)h * 128 * 256;

        // ============ GEMM1: two K-halves, synchronous staging ============
#pragma unroll
        for (int kh = 0; kh < 2; kh++) {
            // stage B half [128 n][128 k] (perm16 within K preserved by linear copy)
#pragma unroll
            for (int it = 0; it < 16; it++) {
                int idx = it * 256 + t;       // 128 rows x 32 float4
                int row = idx >> 5, c4 = idx & 31;
                float4 v = *(const float4*)&img[(size_t)row * 256 + kh * 128 + c4 * 4];
                *(float4*)&smf[B0W + row * BST + c4 * 4] = v;
            }
            __syncthreads();

#pragma unroll
            for (int k16 = 0; k16 < 8; k16++) {
                const int kc = kh * 128 + k16 * 16 + 4 * q;
                uint4 a00 = *(const uint4*)&smu[A0W + ar0 + kc];
                uint4 a01 = *(const uint4*)&smu[A0W + ar1 + kc];
                uint4 a10 = *(const uint4*)&smu[A0W + ar2 + kc];
                uint4 a11 = *(const uint4*)&smu[A0W + ar3 + kc];
#pragma unroll
                for (int nt = 0; nt < 8; nt++) {
                    uint4 bb = *(const uint4*)&smu[B0W + brow + nt * 8 * BST + k16 * 16];
                    mma_tf32(c[0][nt], a00.x, a01.x, a00.y, a01.y, bb.x, bb.y);
                    mma_tf32(c[0][nt], a00.z, a01.z, a00.w, a01.w, bb.z, bb.w);
                    mma_tf32(c[1][nt], a10.x, a11.x, a10.y, a11.y, bb.x, bb.y);
                    mma_tf32(c[1][nt], a10.z, a11.z, a10.w, a11.w, bb.z, bb.w);
                }
            }
            __syncthreads();   // B reads done -> restage / w-f stores
        }

        // ============ softmax (s-half warps -> w) / bias+store (d-half -> f) ============
        float nacc[16];
#pragma unroll
        for (int i = 0; i < 16; i++) nacc[i] = 0.0f;

        if (wn == 0) {
#pragma unroll
            for (int mt = 0; mt < 2; mt++)
#pragma unroll
                for (int rr = 0; rr < 2; rr++) {
                    const int ptok = perm8(wml * 32 + mt * 16 + g + 8 * rr);
                    float pv[16];
                    float mx = -1e30f;
#pragma unroll
                    for (int nt = 0; nt < 8; nt++)
#pragma unroll
                        for (int e = 0; e < 2; e++) {
                            float p = (c[mt][nt][rr * 2 + e] + bias16[nt * 2 + e]) * invt;
                            pv[nt * 2 + e] = p;
                            mx = fmaxf(mx, p);
                        }
                    mx = fmaxf(mx, __shfl_xor_sync(0xffffffffu, mx, 1));
                    mx = fmaxf(mx, __shfl_xor_sync(0xffffffffu, mx, 2));
                    float sv = 0.0f;
#pragma unroll
                    for (int j = 0; j < 16; j++) { pv[j] = __expf(pv[j] - mx); sv += pv[j]; }
                    sv += __shfl_xor_sync(0xffffffffu, sv, 1);
                    sv += __shfl_xor_sync(0xffffffffu, sv, 2);
                    const float r = __fdividef(1.0f, sv);
#pragma unroll
                    for (int nt = 0; nt < 8; nt++)
#pragma unroll
                        for (int e = 0; e < 2; e++) {
                            float wv = pv[nt * 2 + e] * r;
                            nacc[nt * 2 + e] += wv;
                            smu[W0W + (nt * 8 + 2 * q + e) * WST + ptok] = cvt_tf32(wv);
                        }
                }
        } else {
#pragma unroll
            for (int mt = 0; mt < 2; mt++)
#pragma unroll
                for (int rr = 0; rr < 2; rr++) {
                    const int ptok = perm8(wml * 32 + mt * 16 + g + 8 * rr);
#pragma unroll
                    for (int nt = 0; nt < 8; nt++)
#pragma unroll
                        for (int e = 0; e < 2; e++) {
                            float fv = c[mt][nt][rr * 2 + e] + bias16[nt * 2 + e];
                            smu[F0W + (nt * 8 + 2 * q + e) * WST + ptok] = cvt_tf32(fv);
                        }
                }
        }
        __syncthreads();

        // ============ rank update: acc[64 s][64 d] += w^T @ fx (K = 128 tok) ============
        {
            const int wm2 = wp & 3;    // s16 tile
            const int wn2 = wp >> 2;   // d32 group
            float racc[4][4];
#pragma unroll
            for (int i = 0; i < 4; i++)
#pragma unroll
                for (int j = 0; j < 4; j++) racc[i][j] = 0.0f;

#pragma unroll 4
            for (int ks = 0; ks < 16; ks++) {
                const int kc = ks * 8 + 2 * q;
                const int r0 = wm2 * 16 + g;
                uint2 lo = *(const uint2*)&smu[W0W + r0 * WST + kc];
                uint2 hi = *(const uint2*)&smu[W0W + (r0 + 8) * WST + kc];
#pragma unroll
                for (int nt = 0; nt < 4; nt++) {
                    uint2 bb = *(const uint2*)&smu[F0W + (wn2 * 32 + nt * 8 + g) * WST + kc];
                    mma_tf32(racc[nt], lo.x, hi.x, lo.y, hi.y, bb.x, bb.y);
                }
            }

            const int abase = (b * HH + h) * SS;
#pragma unroll
            for (int nt = 0; nt < 4; nt++)
#pragma unroll
                for (int rr = 0; rr < 2; rr++)
#pragma unroll
                    for (int e = 0; e < 2; e++) {
                        int s = wm2 * 16 + g + 8 * rr;
                        int d = wn2 * 32 + nt * 8 + 2 * q + e;
                        atomicAdd(&g_acc[(abase + s) * DD + d], racc[nt][rr * 2 + e]);
                    }
        }

        // ---- norm reduce + atomics (s-half warps) ----
        if (wn == 0) {
#pragma unroll
            for (int j = 0; j < 16; j++) {
                nacc[j] += __shfl_xor_sync(0xffffffffu, nacc[j], 4);
                nacc[j] += __shfl_xor_sync(0xffffffffu, nacc[j], 8);
                nacc[j] += __shfl_xor_sync(0xffffffffu, nacc[j], 16);
            }
            if (g == 0) {
                const int nb = (b * HH + h) * SS;
#pragma unroll
                for (int nt = 0; nt < 8; nt++)
#pragma unroll
                    for (int e = 0; e < 2; e++)
                        atomicAdd(&g_norm[nb + nt * 8 + 2 * q + e], nacc[nt * 2 + e]);
            }
        }
        __syncthreads();   // w/f reads done -> next head may restage B
    }
}

// ------------------------------------------------------------ finalize
__global__ void finalize_kernel(float* __restrict__ out) {
    int i = blockIdx.x * blockDim.x + threadIdx.x;
    if (i < BB * HH * SS * DD)
        out[i] = g_acc[i] / (g_norm[i >> 6] + 0.01f);
}

// -------------------------------------------------------------- launch
extern "C" void kernel_launch(void* const* d_in, const int* in_sizes, int n_in,
                              void* d_out, int out_size) {
    const float* x           = (const float*)d_in[0];
    const float* Wx          = (const float*)d_in[1];
    const float* bx          = (const float*)d_in[2];
    const float* Wfx         = (const float*)d_in[3];
    const float* bfx         = (const float*)d_in[4];
    const float* Wslice      = (const float*)d_in[5];
    const float* bslice      = (const float*)d_in[6];
    const float* temperature = (const float*)d_in[7];
    float* out = (float*)d_out;

    cudaFuncSetAttribute(fused_main, cudaFuncAttributeMaxDynamicSharedMemorySize,
                         SMEM_TOTAL);

    zero_kernel<<<(BB * HH * SS * DD + 255) / 256, 256>>>();
    precompute_kernel<<<HH * CC + 1, 64>>>(Wx, bx, Wslice, bslice);
    build_bt<<<HH, 256>>>(Wfx);
    fused_main<<<NCTA, 256, SMEM_TOTAL>>>(x, bfx, temperature);
    finalize_kernel<<<(BB * HH * SS * DD + 255) / 256, 256>>>(out);
}